// round 9
// baseline (speedup 1.0000x reference)
#include <cuda_runtime.h>
#include <math.h>

#define HH 512
#define WW 512
#define PLANE (512*512)
#define SHAPE_OFF (1*PLANE)
#define SIZE_OFF  (1025*PLANE)
#define HEAT_OFF  (1027*PLANE)
#define NPTS 10
#define MM 128
#define BLKS_PER_HM 32

// per-block partial argmax results; every slot written every run -> no init
__device__ unsigned long long g_partial[NPTS][BLKS_PER_HM];

__device__ __forceinline__ unsigned int fkey(float v) {
    unsigned int b = __float_as_uint(v);
    return (b & 0x80000000u) ? ~b : (b | 0x80000000u);
}
__device__ __forceinline__ unsigned long long umax64(unsigned long long a,
                                                     unsigned long long b) {
    return a > b ? a : b;
}

// 320 blocks (32/heatmap) x 256 threads; 32 floats/thread via 8x float4.
__global__ void __launch_bounds__(256) argmax_kernel(const float* __restrict__ feat) {
    int hm    = blockIdx.x >> 5;
    int chunk = blockIdx.x & 31;
    const float* heat = feat + HEAT_OFF + (size_t)hm * PLANE;
    int base = chunk * 8192;
    int tid = threadIdx.x;

    float bestv = -__int_as_float(0x7F800000);  // -inf
    int   bestq = base;
    float4 bq = make_float4(bestv, bestv, bestv, bestv);

#pragma unroll
    for (int j = 0; j < 8; j++) {
        int e = base + ((j * 256 + tid) << 2);
        float4 v = *reinterpret_cast<const float4*>(heat + e);
        float m = fmaxf(fmaxf(v.x, v.y), fmaxf(v.z, v.w));
        // strict > : on ties the EARLIER quad is kept (e strictly increases)
        if (m > bestv) { bestv = m; bestq = e; bq = v; }
    }

    // first element in winning quad equal to bestv -> global first occurrence
    int off4 = (bq.x == bestv) ? 0 : (bq.y == bestv) ? 1 : (bq.z == bestv) ? 2 : 3;
    int bestidx = bestq + off4;

    unsigned long long best =
        ((unsigned long long)fkey(bestv) << 32) |
        (unsigned int)(~(unsigned int)bestidx);

#pragma unroll
    for (int off = 16; off > 0; off >>= 1)
        best = umax64(best, __shfl_xor_sync(0xFFFFFFFFu, best, off));

    __shared__ unsigned long long s[8];
    if ((tid & 31) == 0) s[tid >> 5] = best;
    __syncthreads();
    if (tid < 32) {
        unsigned long long v = (tid < 8) ? s[tid] : 0ULL;
#pragma unroll
        for (int off = 4; off > 0; off >>= 1)
            v = umax64(v, __shfl_xor_sync(0xFFFFFFFFu, v, off));
        if (tid == 0) g_partial[hm][chunk] = v;
    }
    __syncthreads();
    // PDL: signal dependent grid may launch (all our writes are done)
    asm volatile("griddepcontrol.launch_dependents;" ::: "memory");
}

// grid (NPTS, 64): one block per 2 output rows, 256 threads = one elem each.
__global__ void __launch_bounds__(256) compute_kernel(const float* __restrict__ feat,
                                                      float* __restrict__ out) {
    __shared__ float s_v[2][2][32];   // [row-half][y0/y1][x]
    __shared__ int4 s_meta;

    // PDL: wait until primary grid's writes (g_partial) are visible
    asm volatile("griddepcontrol.wait;" ::: "memory");

    int pt  = blockIdx.x;
    int tid = threadIdx.x;

    // reduce 32 partials in warp 0, resolve idx + sizes
    if (tid < 32) {
        unsigned long long v = g_partial[pt][tid];
#pragma unroll
        for (int off = 16; off > 0; off >>= 1)
            v = umax64(v, __shfl_xor_sync(0xFFFFFFFFu, v, off));
        if (tid == 0) {
            int idx = (int)(~(unsigned int)(v & 0xFFFFFFFFu));
            float hv = fabsf(feat[SIZE_OFF + idx]);
            float wv = fabsf(feat[SIZE_OFF + PLANE + idx]);
            int h = min(max((int)hv, 1), MM);
            int w = min(max((int)wv, 1), MM);
            s_meta = make_int4(idx, h, w, 0);
        }
    }
    __syncthreads();

    int pbase = s_meta.x;
    int h = s_meta.y, w = s_meta.z;
    int py = pbase >> 9;
    int px = pbase & 511;
    float hf = (float)h, wf = (float)w;

    int half = tid >> 7;               // 0 or 1
    int c    = tid & 127;              // column
    int r    = blockIdx.y * 2 + half;  // output row

    float sy = ((float)r + 0.5f) * 32.0f / hf - 0.5f;
    sy = fminf(fmaxf(sy, 0.0f), 31.0f);
    int y0 = (int)floorf(sy);
    int y1 = min(y0 + 1, 31);
    float wy = sy - (float)y0;

    // saliency load: independent of shape gathers -> issued before barrier
    int gr = py - (h >> 1) + r;
    int gc = px - (w >> 1) + c;
    bool valid = (r < h) && (c < w) &&
                 (gr >= 0) && (gr < HH) && (gc >= 0) && (gc < WW);
    float sal = valid ? feat[gr * WW + gc] : 0.0f;

    // shape row gathers (64 scattered loads per half, parallel with sal)
    if (c < 32) {
        s_v[half][0][c] = feat[SHAPE_OFF + (size_t)(y0 * 32 + c) * PLANE + pbase];
    } else if (c < 64) {
        int x = c - 32;
        s_v[half][1][x] = feat[SHAPE_OFF + (size_t)(y1 * 32 + x) * PLANE + pbase];
    }
    __syncthreads();

    float sx = ((float)c + 0.5f) * 32.0f / wf - 0.5f;
    sx = fminf(fmaxf(sx, 0.0f), 31.0f);
    int x0 = (int)floorf(sx);
    int x1 = min(x0 + 1, 31);
    float wx = sx - (float)x0;

    float a0 = s_v[half][0][x0] * (1.0f - wy) + s_v[half][1][x0] * wy;
    float a1 = s_v[half][0][x1] * (1.0f - wy) + s_v[half][1][x1] * wy;
    float v = a0 * (1.0f - wx) + a1 * wx;
    float lv = 1.0f / (1.0f + __expf(-v));

    out[(size_t)pt * (MM * MM) + (size_t)r * MM + c] = valid ? lv * sal : 0.0f;
}

extern "C" void kernel_launch(void* const* d_in, const int* in_sizes, int n_in,
                              void* d_out, int out_size) {
    const float* feat = (const float*)d_in[0];
    float* out = (float*)d_out;

    argmax_kernel<<<NPTS * BLKS_PER_HM, 256>>>(feat);

    // secondary with programmatic stream serialization (PDL)
    cudaLaunchConfig_t cfg = {};
    cfg.gridDim  = dim3(NPTS, MM / 2);
    cfg.blockDim = dim3(256);
    cfg.dynamicSmemBytes = 0;
    cudaLaunchAttribute attr[1];
    attr[0].id = cudaLaunchAttributeProgrammaticStreamSerialization;
    attr[0].val.programmaticStreamSerializationAllowed = 1;
    cfg.attrs = attr;
    cfg.numAttrs = 1;
    cudaLaunchKernelEx(&cfg, compute_kernel, feat, out);
}